// round 1
// baseline (speedup 1.0000x reference)
#include <cuda_runtime.h>
#include <cuda_bf16.h>

// Problem shape (from reference setup_inputs): P=4096, N=8192, L=4096.
// q[i] = sum_j relu(neg[j] - pos[i] + DELTA)
// out[0..L)      = lambdas with out[idx[i]] += mu*q[i]   (unique indices)
// out[out_size-1]= (mu/2 * q[P-1]^2 + lambdas[idx[P-1]] * q[P-1]) / (P*N)

#define ALM_DELTA 0.1f

static constexpr int MAX_P  = 4096;
static constexpr int JB     = 16;        // number of j-chunks
static constexpr int BLK    = 256;       // threads per block (one i per thread)

// Scratch (allocation-free rule: __device__ globals)
__device__ float g_qpart[JB * MAX_P];
__device__ float g_q[MAX_P];

// ---------------------------------------------------------------------------
// Kernel 1: pairwise relu-margin partial sums.
// grid = (P/BLK, JB). Each block caches one neg chunk in smem; each thread
// owns one i and accumulates over the chunk. smem reads are pure broadcast.
// ---------------------------------------------------------------------------
__global__ void k_pairwise(const float* __restrict__ pos,
                           const float* __restrict__ neg,
                           int P, int N, int chunk) {
    extern __shared__ float s_neg[];
    const int jb  = blockIdx.y;
    const int j0  = jb * chunk;
    for (int j = threadIdx.x; j < chunk; j += blockDim.x)
        s_neg[j] = neg[j0 + j];
    __syncthreads();

    const int i = blockIdx.x * blockDim.x + threadIdx.x;
    if (i >= P) return;

    const float posd = pos[i] - ALM_DELTA;   // relu(neg - pos + d) = max(neg - (pos-d), 0)

    // 4 independent accumulators for ILP (FADD lat 4, rt 2 on fma pipe)
    float a0 = 0.f, a1 = 0.f, a2 = 0.f, a3 = 0.f;
    int j = 0;
    for (; j + 4 <= chunk; j += 4) {
        a0 += fmaxf(s_neg[j + 0] - posd, 0.f);
        a1 += fmaxf(s_neg[j + 1] - posd, 0.f);
        a2 += fmaxf(s_neg[j + 2] - posd, 0.f);
        a3 += fmaxf(s_neg[j + 3] - posd, 0.f);
    }
    for (; j < chunk; ++j)
        a0 += fmaxf(s_neg[j] - posd, 0.f);

    g_qpart[jb * P + i] = (a0 + a1) + (a2 + a3);
}

// ---------------------------------------------------------------------------
// Kernel 2: reduce JB partials into g_q[i]; copy lambdas -> out.
// ---------------------------------------------------------------------------
__global__ void k_reduce_copy(const float* __restrict__ lambdas,
                              float* __restrict__ out,
                              int P, int L) {
    const int i = blockIdx.x * blockDim.x + threadIdx.x;
    if (i < L) out[i] = lambdas[i];
    if (i < P) {
        float s = 0.f;
        #pragma unroll
        for (int jb = 0; jb < JB; ++jb)
            s += g_qpart[jb * P + i];
        g_q[i] = s;
    }
}

// ---------------------------------------------------------------------------
// Kernel 3: scatter-add mu*q into out; last thread writes the loss scalar.
// lambdas[] read here is the ORIGINAL input (loss uses pre-update lambda).
// ---------------------------------------------------------------------------
__global__ void k_scatter_loss(const int* __restrict__ idx,
                               const float* __restrict__ lambdas,
                               const float* __restrict__ mu,
                               float* __restrict__ out,
                               int P, int N, int L, int out_size) {
    const int i = blockIdx.x * blockDim.x + threadIdx.x;
    if (i >= P) return;
    const float m = mu[0];
    atomicAdd(&out[idx[i]], m * g_q[i]);
    if (i == P - 1 && out_size > L) {
        const float q   = g_q[i];
        const float lam = lambdas[idx[i]];
        const float loss = (0.5f * m * q * q + lam * q) / ((float)P * (float)N);
        out[out_size - 1] = loss;
    }
}

extern "C" void kernel_launch(void* const* d_in, const int* in_sizes, int n_in,
                              void* d_out, int out_size) {
    const float* pos     = (const float*)d_in[0];   // buffer_batch_pos [P]
    const float* neg     = (const float*)d_in[1];   // buffer_batch_neg [N]
    const int*   idx     = (const int*)  d_in[2];   // lambdas_index_buffer [P] (int32)
    const float* lambdas = (const float*)d_in[3];   // lambdas [L]
    const float* mu      = (const float*)d_in[4];   // mu [1]
    float* out = (float*)d_out;

    const int P = in_sizes[0];
    const int N = in_sizes[1];
    const int L = in_sizes[3];

    const int chunk = (N + JB - 1) / JB;            // 512 for N=8192

    dim3 grid1((P + BLK - 1) / BLK, JB);
    k_pairwise<<<grid1, BLK, chunk * sizeof(float)>>>(pos, neg, P, N, chunk);

    const int maxPL = (P > L) ? P : L;
    k_reduce_copy<<<(maxPL + BLK - 1) / BLK, BLK>>>(lambdas, out, P, L);

    k_scatter_loss<<<(P + BLK - 1) / BLK, BLK>>>(idx, lambdas, mu, out, P, N, L, out_size);
}